// round 8
// baseline (speedup 1.0000x reference)
#include <cuda_runtime.h>
#include <cuda_pipeline.h>

#define DIM 1024
#define NROWS 32        // B*T = 2*16 distinct kv rows
#define TPF 1560        // tokens per frame
#define GRID 256
#define ROWS_PER_CTA 195   // 32*1560 / 256; 1560/195 = 8 -> one frame per CTA

// Scratch + barrier state (no cudaMalloc allowed). Zero-initialized once.
__device__ float g_v[NROWS * DIM];
__device__ float g_y[NROWS * DIM];
__device__ unsigned g_bar1;
__device__ unsigned g_bar2;

#define KCH 256                               // K per pipeline chunk
#define STAGE_FLOATS ((8 + 16) * KCH)         // 24KB per stage
#define SMEM_BYTES (2 * STAGE_FLOATS * 4)     // 48KB ring

// One 16x8 output tile of  OUT = IN @ W^T + bias  (IN: [32,1024], W: [1024,1024]).
// 2-stage cp.async pipeline over 4 K-chunks; 4x4 register tile per warp,
// K split across lanes, butterfly reduction. (Identical to the R7 kernel body.)
__device__ __forceinline__ void gemm_tile(
    float* s, const float* __restrict__ in, const float* __restrict__ W,
    const float* __restrict__ bias, float* __restrict__ out,
    int row0, int col0, int tid)
{
    const int lane = tid & 31;
    const int warp = tid >> 5;
    const int rg   = warp & 3;
    const int cg   = warp >> 2;

    const float4* Wg = reinterpret_cast<const float4*>(W + (size_t)col0 * DIM);
    const float4* Xg = reinterpret_cast<const float4*>(in + (size_t)row0 * DIM);

    auto stage_chunk = [&](int ch, int st) {
        float4* sW4 = reinterpret_cast<float4*>(s + st * STAGE_FLOATS);
        float4* sX4 = sW4 + 8 * (KCH / 4);
        const int k4 = ch * (KCH / 4);
        #pragma unroll
        for (int f = tid; f < 8 * 64; f += 256) {
            int c = f >> 6, j = f & 63;
            __pipeline_memcpy_async(&sW4[f], &Wg[(size_t)c * 256 + k4 + j], 16);
        }
        #pragma unroll
        for (int f = tid; f < 16 * 64; f += 256) {
            int r = f >> 6, j = f & 63;
            __pipeline_memcpy_async(&sX4[f], &Xg[(size_t)r * 256 + k4 + j], 16);
        }
        __pipeline_commit();
    };

    float acc[4][4];
    #pragma unroll
    for (int r = 0; r < 4; r++)
        #pragma unroll
        for (int c = 0; c < 4; c++) acc[r][c] = 0.0f;

    stage_chunk(0, 0);

    #pragma unroll
    for (int ch = 0; ch < 4; ch++) {
        const int st = ch & 1;
        if (ch < 3) stage_chunk(ch + 1, st ^ 1);
        __pipeline_wait_prior(ch < 3 ? 1 : 0);
        __syncthreads();

        const float* sW = s + st * STAGE_FLOATS;          // [8][256]
        const float* sX = sW + 8 * KCH;                   // [16][256]
        #pragma unroll
        for (int half = 0; half < 2; half++) {
            const int k = half * 128 + lane * 4;
            float4 w[4], x[4];
            #pragma unroll
            for (int c = 0; c < 4; c++)
                w[c] = *reinterpret_cast<const float4*>(&sW[(cg * 4 + c) * KCH + k]);
            #pragma unroll
            for (int r = 0; r < 4; r++)
                x[r] = *reinterpret_cast<const float4*>(&sX[(rg * 4 + r) * KCH + k]);
            #pragma unroll
            for (int r = 0; r < 4; r++)
                #pragma unroll
                for (int c = 0; c < 4; c++)
                    acc[r][c] += x[r].x * w[c].x + x[r].y * w[c].y
                               + x[r].z * w[c].z + x[r].w * w[c].w;
        }
        __syncthreads();
    }

    #pragma unroll
    for (int off = 16; off; off >>= 1)
        #pragma unroll
        for (int r = 0; r < 4; r++)
            #pragma unroll
            for (int c = 0; c < 4; c++)
                acc[r][c] += __shfl_xor_sync(0xffffffffu, acc[r][c], off);

    float res = 0.0f;
    #pragma unroll
    for (int r = 0; r < 4; r++)
        #pragma unroll
        for (int c = 0; c < 4; c++)
            if (lane == r * 4 + c) res = acc[r][c];

    if (lane < 16) {
        const int r = lane >> 2, c = lane & 3;
        const int grow = row0 + rg * 4 + r;
        const int gcol = col0 + cg * 4 + c;
        out[grow * DIM + gcol] = res + bias[gcol];
    }
}

// Grid-wide spin barrier. All GRID CTAs are co-resident (grid=256 <= 296
// capacity at 48KB smem / <=128 regs), so spinning is deadlock-free.
// The fence before the arrival gives release; the RMW + fence after gives acquire.
__device__ __forceinline__ void grid_barrier(unsigned* ctr,
                                             unsigned* reset_when_done)
{
    __syncthreads();
    __threadfence();
    if (threadIdx.x == 0) {
        unsigned old = atomicAdd(ctr, 1);
        if (reset_when_done && old == GRID - 1)
            atomicExch(reset_when_done, 0);       // safe: all passed that barrier
        while (*(volatile unsigned*)ctr < GRID) __nanosleep(64);
        __threadfence();
    }
    __syncthreads();
}

// ONE launch: v = c@Wv^T+bv ; barrier ; y = v@Wo^T+bo ; barrier ; broadcast.
__global__ __launch_bounds__(256, 2) void fused_kernel(
    const float* __restrict__ c,
    const float* __restrict__ Wv, const float* __restrict__ bv,
    const float* __restrict__ Wo, const float* __restrict__ bo,
    float* __restrict__ out)
{
    extern __shared__ float s[];
    const int tid = threadIdx.x;
    const int bx  = blockIdx.x;

    // Reset bar2 (left at GRID by the previous replay). Race-free: no CTA can
    // reach bar2 before bar1 releases, which requires THIS CTA's fenced arrival,
    // which is ordered after this reset.
    if (bx == 0 && tid == 0) atomicExch(&g_bar2, 0);

    const int cb   = bx & 127;               // col block (8 cols)
    const int rb   = bx >> 7;                // row block (16 rows)
    const int row0 = rb * 16;
    const int col0 = cb * 8;

    // Phase A: v tile
    gemm_tile(s, c, Wv, bv, g_v, row0, col0, tid);
    grid_barrier(&g_bar1, nullptr);

    // Phase B: y tile (v is L2-hot)
    gemm_tile(s, g_v, Wo, bo, g_y, row0, col0, tid);
    grid_barrier(&g_bar2, &g_bar1);          // last arriver resets bar1 for next replay

    // Phase C: broadcast. CTA bx owns 195 consecutive token-rows, all in
    // frame bx/8 (195*8 == 1560). Source value is loop-invariant.
    const int f = bx >> 3;
    const float4 val = reinterpret_cast<const float4*>(g_y)[f * 256 + tid];
    float4* dst = reinterpret_cast<float4*>(out) + (size_t)bx * ROWS_PER_CTA * 256 + tid;
    #pragma unroll 5
    for (int r = 0; r < ROWS_PER_CTA; r++)
        __stcs(dst + (size_t)r * 256, val);
}

extern "C" void kernel_launch(void* const* d_in, const int* in_sizes, int n_in,
                              void* d_out, int out_size)
{
    // metadata order: x, c, Wq, bq, Wk, bk, Wv, bv, Wo, bo
    // softmax over a length-1 kv axis is identically 1 -> x/Wq/bq/Wk/bk unused.
    const float* c  = (const float*)d_in[1];
    const float* Wv = (const float*)d_in[6];
    const float* bv = (const float*)d_in[7];
    const float* Wo = (const float*)d_in[8];
    const float* bo = (const float*)d_in[9];
    float* out = (float*)d_out;

    cudaFuncSetAttribute(fused_kernel,
                         cudaFuncAttributeMaxDynamicSharedMemorySize, SMEM_BYTES);

    fused_kernel<<<GRID, 256, SMEM_BYTES>>>(c, Wv, bv, Wo, bo, out);

    (void)in_sizes; (void)n_in; (void)out_size;
}

// round 9
// speedup vs baseline: 1.6044x; 1.6044x over previous
#include <cuda_runtime.h>
#include <cuda_pipeline.h>

#define DIM 1024
#define NROWS 32        // B*T = 2*16 distinct kv rows
#define TPF 1560        // tokens per frame

// Scratch (no cudaMalloc allowed): intermediate v and final per-frame y.
__device__ float g_v[NROWS * DIM];
__device__ float g_y[NROWS * DIM];

#define KCH 256                               // K per pipeline chunk
#define NSTAGE 3
#define STAGE_FLOATS ((8 + 16) * KCH)         // 24KB per stage
#define SMEM_BYTES (NSTAGE * STAGE_FLOATS * 4)  // 72KB ring

// ---- packed fp32x2 helpers (fp32-exact, halves FFMA issue count) ----
__device__ __forceinline__ unsigned long long pk(float lo, float hi) {
    unsigned long long r;
    asm("mov.b64 %0, {%1, %2};" : "=l"(r) : "f"(lo), "f"(hi));
    return r;
}
__device__ __forceinline__ void fma2(unsigned long long& a,
                                     unsigned long long x, unsigned long long w) {
    asm("fma.rn.f32x2 %0, %1, %2, %0;" : "+l"(a) : "l"(x), "l"(w));
}
__device__ __forceinline__ float2 unpk(unsigned long long a) {
    float lo, hi;
    asm("mov.b64 {%0, %1}, %2;" : "=f"(lo), "=f"(hi) : "l"(a));
    return make_float2(lo, hi);
}

// OUT[r, col] = sum_k IN[r, k] * W[col, k] + bias[col]
// IN: [32, 1024], W: [1024, 1024] row-major  (=> IN @ W^T + b)
//
// 3-stage cp.async ring over 4 K-chunks of 256. Refill target at iter ch is
// the stage consumed at iter ch-1, already protected by this iter's barrier,
// so only ONE __syncthreads per iteration. Inner product uses packed
// fma.rn.f32x2 (2 fp32 MACs/instr). Optional `pf` L2-prefetches the NEXT
// GEMM's weight tile so its DRAM latency is paid here, under compute.
// Block = 8 warps = 4 row-groups x 2 col-groups = 16 rows x 8 cols.
// Grid = 256 (128 col-blocks x 2 row-blocks).
__global__ __launch_bounds__(256) void gemm32_kernel(
    const float* __restrict__ in,
    const float* __restrict__ W,
    const float* __restrict__ bias,
    float* __restrict__ out,
    const float* __restrict__ pf)     // next-GEMM weights to prefetch (or null)
{
    extern __shared__ float s[];

    const int tid  = threadIdx.x;
    const int lane = tid & 31;
    const int warp = tid >> 5;
    const int rg   = warp & 3;
    const int cg   = warp >> 2;
    const int cb   = blockIdx.x & 127;       // col block (8 cols)
    const int rb   = blockIdx.x >> 7;        // row block (16 rows)
    const int row0 = rb * 16;
    const int col0 = cb * 8;

    const float4* Wg = reinterpret_cast<const float4*>(W + (size_t)col0 * DIM);
    const float4* Xg = reinterpret_cast<const float4*>(in + (size_t)row0 * DIM);

    auto stage_chunk = [&](int ch, int st) {
        float4* sW4 = reinterpret_cast<float4*>(s + st * STAGE_FLOATS);
        float4* sX4 = sW4 + 8 * (KCH / 4);
        const int k4 = ch * (KCH / 4);
        #pragma unroll
        for (int f = tid; f < 8 * 64; f += 256) {
            int c = f >> 6, j = f & 63;
            __pipeline_memcpy_async(&sW4[f], &Wg[(size_t)c * 256 + k4 + j], 16);
        }
        #pragma unroll
        for (int f = tid; f < 16 * 64; f += 256) {
            int r = f >> 6, j = f & 63;
            __pipeline_memcpy_async(&sX4[f], &Xg[(size_t)r * 256 + k4 + j], 16);
        }
        __pipeline_commit();
    };

    stage_chunk(0, 0);
    stage_chunk(1, 1);

    // L2-prefetch the next GEMM's W tile (same tile mapping): 256 lines, 1/thread.
    if (pf) {
        const char* base = reinterpret_cast<const char*>(pf) + (size_t)col0 * DIM * 4;
        asm volatile("prefetch.global.L2 [%0];" :: "l"(base + tid * 128));
    }

    unsigned long long acc2[4][4];
    #pragma unroll
    for (int r = 0; r < 4; r++)
        #pragma unroll
        for (int c = 0; c < 4; c++) acc2[r][c] = 0ull;

    #pragma unroll
    for (int ch = 0; ch < 4; ch++) {
        const int st = ch % NSTAGE;
        __pipeline_wait_prior(ch < 3 ? 1 : 0);   // chunk ch landed (1 outstanding)
        __syncthreads();                          // all warps' copies visible; all past ch-1
        if (ch < 2) stage_chunk(ch + 2, (ch + 2) % NSTAGE);  // safe: consumed at ch-1

        const float* sW = s + st * STAGE_FLOATS;          // [8][256]
        const float* sX = sW + 8 * KCH;                   // [16][256]
        #pragma unroll
        for (int half = 0; half < 2; half++) {
            const int k = half * 128 + lane * 4;
            unsigned long long wlo[4], whi[4], xlo[4], xhi[4];
            #pragma unroll
            for (int c = 0; c < 4; c++) {
                float4 w = *reinterpret_cast<const float4*>(&sW[(cg * 4 + c) * KCH + k]);
                wlo[c] = pk(w.x, w.y); whi[c] = pk(w.z, w.w);
            }
            #pragma unroll
            for (int r = 0; r < 4; r++) {
                float4 x = *reinterpret_cast<const float4*>(&sX[(rg * 4 + r) * KCH + k]);
                xlo[r] = pk(x.x, x.y); xhi[r] = pk(x.z, x.w);
            }
            #pragma unroll
            for (int r = 0; r < 4; r++)
                #pragma unroll
                for (int c = 0; c < 4; c++) {
                    fma2(acc2[r][c], xlo[r], wlo[c]);
                    fma2(acc2[r][c], xhi[r], whi[c]);
                }
        }
    }

    // Collapse packed halves, then butterfly-reduce across lanes.
    float acc[4][4];
    #pragma unroll
    for (int r = 0; r < 4; r++)
        #pragma unroll
        for (int c = 0; c < 4; c++) {
            float2 p = unpk(acc2[r][c]);
            acc[r][c] = p.x + p.y;
        }
    #pragma unroll
    for (int off = 16; off; off >>= 1)
        #pragma unroll
        for (int r = 0; r < 4; r++)
            #pragma unroll
            for (int c = 0; c < 4; c++)
                acc[r][c] += __shfl_xor_sync(0xffffffffu, acc[r][c], off);

    // Lane (r*4 + c), lanes 0..15, writes (row0 + rg*4 + r, col0 + cg*4 + c).
    float res = 0.0f;
    #pragma unroll
    for (int r = 0; r < 4; r++)
        #pragma unroll
        for (int c = 0; c < 4; c++)
            if (lane == r * 4 + c) res = acc[r][c];

    if (lane < 16) {
        const int r = lane >> 2, c = lane & 3;
        const int grow = row0 + rg * 4 + r;
        const int gcol = col0 + cg * 4 + c;
        out[grow * DIM + gcol] = res + bias[gcol];
    }
}

// Broadcast y[frame, :] (1024 fp32 = 256 float4) to all 1560 rows of the frame.
// Source value is loop-invariant per thread -> pure coalesced streaming stores.
// This kernel is at ~96% of the 204MB DRAM write floor already.
__global__ __launch_bounds__(256) void bcast_kernel(
    const float4* __restrict__ y4,
    float4* __restrict__ out4)
{
    const int f   = blockIdx.y;                  // frame 0..31
    const int tid = threadIdx.x;
    const float4 val = y4[f * 256 + tid];

    const int per_frame = TPF * 256;             // 399,360 float4 per frame
    const long base = (long)f * per_frame;
    const int stride = gridDim.x * 256;

    for (int i = blockIdx.x * 256 + tid; i < per_frame; i += stride) {
        __stcs(&out4[base + i], val);            // streaming store: don't churn L2
    }
}

extern "C" void kernel_launch(void* const* d_in, const int* in_sizes, int n_in,
                              void* d_out, int out_size)
{
    // metadata order: x, c, Wq, bq, Wk, bk, Wv, bv, Wo, bo
    // softmax over a length-1 kv axis is identically 1 -> x/Wq/bq/Wk/bk unused.
    const float* c  = (const float*)d_in[1];
    const float* Wv = (const float*)d_in[6];
    const float* bv = (const float*)d_in[7];
    const float* Wo = (const float*)d_in[8];
    const float* bo = (const float*)d_in[9];
    float* out = (float*)d_out;

    void* vptr = nullptr;
    void* yptr = nullptr;
    cudaGetSymbolAddress(&vptr, g_v);
    cudaGetSymbolAddress(&yptr, g_y);
    float* v = (float*)vptr;
    float* y = (float*)yptr;

    cudaFuncSetAttribute(gemm32_kernel,
                         cudaFuncAttributeMaxDynamicSharedMemorySize, SMEM_BYTES);

    // v = c @ Wv^T + bv   (prefetch Wo into L2 under this kernel's compute)
    gemm32_kernel<<<256, 256, SMEM_BYTES>>>(c, Wv, bv, v, Wo);
    // y = v @ Wo^T + bo   (Wo now L2-hot)
    gemm32_kernel<<<256, 256, SMEM_BYTES>>>(v, Wo, bo, y, nullptr);
    // out[b, t*1560+i, :] = y[b,t,:]   (204 MB broadcast store)
    bcast_kernel<<<dim3(130, 32), 256>>>((const float4*)y, (float4*)out);

    (void)in_sizes; (void)n_in; (void)out_size;
}